// round 12
// baseline (speedup 1.0000x reference)
#include <cuda_runtime.h>
#include <cuda_fp16.h>
#include <math.h>
#include <stdint.h>

#define B   2
#define L   2048
#define EMB 2048
#define NH  16
#define HD  128
#define NTOT 2304          // 2048 Q cols + 128 K + 128 V

// ---------------- scratch (device globals: no allocation allowed) -------------
__device__ __half g_Qh[2 * 16 * 2048 * 128];  // [B][NH][L][HD] RoPE'd fp16
__device__ __half g_Kh[2 * 2048 * 128];       // [B][L][HD] RoPE'd
__device__ __half g_Vh[2 * 2048 * 128];
__device__ float  g_Rc[2048 * 64];
__device__ float  g_Rs[2048 * 64];
__device__ __half g_Xh[4096 * 2048];          // X fp16
__device__ __half g_Wth[NTOT * 2048];         // W^T fp16 [n][k]

// ---------------- PTX helpers ---------------------------------------------------
__device__ __forceinline__ uint32_t smem_u32(const void* p) {
    uint32_t a;
    asm("{ .reg .u64 t; cvta.to.shared.u64 t, %1; cvt.u32.u64 %0, t; }" : "=r"(a) : "l"(p));
    return a;
}
__device__ __forceinline__ void cpa16(uint32_t dst, const void* src) {
    asm volatile("cp.async.cg.shared.global [%0], [%1], 16;" :: "r"(dst), "l"(src));
}
#define CPA_COMMIT() asm volatile("cp.async.commit_group;" ::: "memory")
#define CPA_WAIT0()  asm volatile("cp.async.wait_group 0;" ::: "memory")
#define CPA_WAIT1()  asm volatile("cp.async.wait_group 1;" ::: "memory")

__device__ __forceinline__ void ldm_x4(uint32_t* r, uint32_t addr) {
    asm volatile("ldmatrix.sync.aligned.m8n8.x4.shared.b16 {%0,%1,%2,%3}, [%4];"
        : "=r"(r[0]), "=r"(r[1]), "=r"(r[2]), "=r"(r[3]) : "r"(addr));
}
__device__ __forceinline__ void ldm_x4_t(uint32_t* r, uint32_t addr) {
    asm volatile("ldmatrix.sync.aligned.m8n8.x4.trans.shared.b16 {%0,%1,%2,%3}, [%4];"
        : "=r"(r[0]), "=r"(r[1]), "=r"(r[2]), "=r"(r[3]) : "r"(addr));
}
__device__ __forceinline__ void mma_f16(float* c, const uint32_t* a, const uint32_t* b) {
    asm volatile("mma.sync.aligned.m16n8k16.row.col.f32.f16.f16.f32 "
        "{%0,%1,%2,%3}, {%4,%5,%6,%7}, {%8,%9}, {%0,%1,%2,%3};"
        : "+f"(c[0]), "+f"(c[1]), "+f"(c[2]), "+f"(c[3])
        : "r"(a[0]), "r"(a[1]), "r"(a[2]), "r"(a[3]), "r"(b[0]), "r"(b[1]));
}
__device__ __forceinline__ uint32_t packh2(float a, float b) {
    __half2 h = __floats2half2_rn(a, b);
    return *(uint32_t*)&h;
}
__device__ __forceinline__ float ex2(float x) {
    float y;
    asm("ex2.approx.f32 %0, %1;" : "=f"(y) : "f"(x));
    return y;
}

// ---------------- fused prepass: rope table | X fp16 | W^T fp16 -----------------
__global__ void prep_kernel(const float* __restrict__ X,
                            const float* __restrict__ Wq,
                            const float* __restrict__ Wk,
                            const float* __restrict__ Wv) {
    __shared__ float tile[32][33];
    int bid = blockIdx.x;
    if (bid < 512) {
        int idx = bid * 256 + threadIdx.x;        // 2048*64
        int l = idx >> 6;
        int i = idx & 63;
        double invf = pow(10000.0, -(double)(2 * i) / (double)HD);
        double a = (double)l * invf;
        g_Rc[idx] = (float)cos(a);
        g_Rs[idx] = (float)sin(a);
    } else if (bid < 512 + 8192) {
        int i = ((bid - 512) * 256 + threadIdx.x) * 4;
        float4 v = *(const float4*)(X + i);
        float vv[4] = {v.x, v.y, v.z, v.w};
        __half h[4];
#pragma unroll
        for (int j = 0; j < 4; j++) h[j] = __float2half_rn(vv[j]);
        *(uint2*)(g_Xh + i) = *(uint2*)h;
    } else {
        int r = bid - 8704;
        int kb = (r & 63) * 32;
        int nb = (r >> 6) * 32;
        const float* W; int ldw, n0;
        if (nb < 2048)      { W = Wq; ldw = 2048; n0 = nb; }
        else if (nb < 2176) { W = Wk; ldw = 128;  n0 = nb - 2048; }
        else                { W = Wv; ldw = 128;  n0 = nb - 2176; }
        int tx = threadIdx.x & 31, ty = threadIdx.x >> 5;
#pragma unroll
        for (int rr = 0; rr < 32; rr += 8)
            tile[ty + rr][tx] = W[(size_t)(kb + ty + rr) * ldw + n0 + tx];
        __syncthreads();
#pragma unroll
        for (int rr = 0; rr < 32; rr += 8)
            g_Wth[(size_t)(nb + ty + rr) * 2048 + kb + tx] =
                __float2half_rn(tile[tx][ty + rr]);
    }
}

// ---------------- QKV GEMM: fp16 mma.sync, BK=64, 3-stage pipeline --------------
// Grid (18, 32), 256 thr = 8 warps (4m x 2n). Tile 128x128, BK=64.
// smem/stage: Xh | Wh tiles, 128 rows x 144B each; 3 stages = 110592B.
#define TS      144
#define TILE_B  (128 * TS)          // 18432
#define STG_B   (2 * TILE_B)        // 36864
#define NCHUNK  32

__device__ __forceinline__ void load_chunk(uint32_t sbase, int stage,
                                           int m0, int n0, int kc, int t) {
    uint32_t sb = sbase + stage * STG_B;
#pragma unroll
    for (int it = 0; it < 8; it++) {
        int g = t + 256 * it;               // 0..2047
        int tile = g >> 10;
        int r = (g >> 3) & 127;
        int c = g & 7;
        uint32_t dst = sb + tile * TILE_B + r * TS + c * 16;
        const __half* src;
        if (tile == 0) src = g_Xh  + (size_t)(m0 + r) * EMB + kc + c * 8;
        else           src = g_Wth + (size_t)(n0 + r) * EMB + kc + c * 8;
        cpa16(dst, src);
    }
}

__global__ __launch_bounds__(256, 2) void qkv_gemm_kernel() {
    extern __shared__ char smem[];
    uint32_t sbase = smem_u32(smem);
    int t = threadIdx.x;
    int lane = t & 31, w = t >> 5;
    int wm = w & 3, wn = w >> 2;
    int nb = blockIdx.x;
    int m0 = blockIdx.y * 128;
    int n0 = nb * 128;

    float acc[2][8][4];
#pragma unroll
    for (int i = 0; i < 2; i++)
#pragma unroll
        for (int j = 0; j < 8; j++)
#pragma unroll
            for (int q = 0; q < 4; q++) acc[i][j][q] = 0.f;

    int aRow = wm * 32 + (lane & 15);
    uint32_t aOff = (uint32_t)(aRow * TS + ((lane >> 4) << 4));
    int bRow = wn * 64 + ((lane >> 4) << 3) + (lane & 7);
    uint32_t bOff = (uint32_t)(bRow * TS + (((lane >> 3) & 1) << 4));

    load_chunk(sbase, 0, m0, n0, 0, t);
    CPA_COMMIT();
    load_chunk(sbase, 1, m0, n0, 64, t);
    CPA_COMMIT();

    for (int i = 0; i < NCHUNK; i++) {
        if (i < NCHUNK - 1) CPA_WAIT1(); else CPA_WAIT0();
        __syncthreads();
        if (i + 2 < NCHUNK) {
            load_chunk(sbase, (i + 2) % 3, m0, n0, (i + 2) * 64, t);
            CPA_COMMIT();
        }

        uint32_t sb = sbase + (i % 3) * STG_B;
#pragma unroll
        for (int ks = 0; ks < 4; ks++) {
            uint32_t kb = ks * 32;
            uint32_t ah[2][4];
#pragma unroll
            for (int mf = 0; mf < 2; mf++)
                ldm_x4(ah[mf], sb + aOff + (uint32_t)(mf * 16 * TS) + kb);
#pragma unroll
            for (int ng = 0; ng < 4; ng++) {
                uint32_t bh[4];
                ldm_x4(bh, sb + TILE_B + bOff + (uint32_t)(ng * 16 * TS) + kb);
#pragma unroll
                for (int sub = 0; sub < 2; sub++) {
                    int nf = ng * 2 + sub;
                    mma_f16(acc[0][nf], ah[0], bh + 2 * sub);
                    mma_f16(acc[1][nf], ah[1], bh + 2 * sub);
                }
            }
        }
    }

    // epilogue: RoPE (Q,K) + fp16 scatter
#pragma unroll
    for (int mf = 0; mf < 2; mf++) {
#pragma unroll
        for (int half = 0; half < 2; half++) {
            int row = m0 + wm * 32 + mf * 16 + (lane >> 2) + half * 8;
            int bb = row >> 11;
            int l  = row & 2047;
#pragma unroll
            for (int nf = 0; nf < 8; nf++) {
                int dcol = wn * 64 + nf * 8 + ((lane & 3) << 1);
                float e = acc[mf][nf][half * 2 + 0];
                float o = acc[mf][nf][half * 2 + 1];
                float2 v;
                if (nb != 17) {
                    float c  = g_Rc[l * 64 + (dcol >> 1)];
                    float sn = g_Rs[l * 64 + (dcol >> 1)];
                    v.x = e * c - o * sn;
                    v.y = o * c + e * sn;
                } else {
                    v.x = e; v.y = o;
                }
                __half2 hp = __floats2half2_rn(v.x, v.y);
                if (nb < 16)
                    *(__half2*)(g_Qh + ((size_t)(bb * NH + nb) * L + l) * HD + dcol) = hp;
                else if (nb == 16)
                    *(__half2*)(g_Kh + (size_t)row * HD + dcol) = hp;
                else
                    *(__half2*)(g_Vh + (size_t)row * HD + dcol) = hp;
            }
        }
    }
}

// ---------------- causal flash attention: fp16 mma.sync, BQ=256, 512 thr --------
// Grid (8 qtiles LPT, 16 h, 2 b), 512 thr = 16 warps (16 q-rows each).
// smem: Q (256x272) + 2 KV stages (Kh|Vh 64x272 each) = 139264 B, 1 CTA/SM.
#define ROWB 272
#define QT_B 69632          // 256*272
#define KT_B 17408
#define STAGE0 69632

__device__ __forceinline__ void load_kv(uint32_t sb, int stage, int b, int j0, int t) {
    uint32_t base = sb + STAGE0 + stage * (2 * KT_B);
#pragma unroll
    for (int it = 0; it < 4; it++) {
        int g = t + 512 * it;             // 0..2047
        int tile = g >> 10;               // K, V
        int r = (g >> 4) & 63;
        int c = g & 15;
        size_t off = (size_t)(b * L + j0 + r) * HD + c * 8;
        const __half* src = (tile ? g_Vh : g_Kh) + off;
        cpa16(base + tile * KT_B + r * ROWB + c * 16, src);
    }
}

__global__ __launch_bounds__(512, 1) void attn_kernel(float* __restrict__ out) {
    extern __shared__ char sm[];
    uint32_t sb = smem_u32(sm);
    int t = threadIdx.x;
    int lane = t & 31, wq = t >> 5;        // 16 warps
    int qt = 7 - blockIdx.x;               // LPT: heavy diagonal tiles first
    int h = blockIdx.y, b = blockIdx.z;
    int q0 = qt * 256;

    {
        const __half* Qp = g_Qh + ((size_t)(b * NH + h) * L + q0) * HD;
#pragma unroll
        for (int it = 0; it < 8; it++) {
            int g = t + 512 * it;          // 0..4095
            int r = g >> 4;
            int c = g & 15;
            cpa16(sb + r * ROWB + c * 16, Qp + (size_t)r * HD + c * 8);
        }
    }
    load_kv(sb, 0, b, 0, t);
    CPA_COMMIT();

    float o[16][4];
#pragma unroll
    for (int i = 0; i < 16; i++)
#pragma unroll
        for (int j = 0; j < 4; j++) o[i][j] = 0.f;
    float m1 = -INFINITY, m2 = -INFINITY, l1 = 0.f, l2 = 0.f;

    const float scale = 0.08838834764831845f * 1.44269504088896f;  // /sqrt(HD)*log2e
    int niter = 4 * qt + 4;
    int grow1 = q0 + wq * 16 + (lane >> 2);
    int grow2 = grow1 + 8;

    uint32_t aoff  = (uint32_t)((wq * 16 + (lane & 15)) * ROWB + ((lane >> 4) << 4));
    uint32_t boffK = (uint32_t)((((lane >> 4) << 3) + (lane & 7)) * ROWB
                                + (((lane >> 3) & 1) << 4));
    uint32_t voff  = (uint32_t)(((((lane >> 3) & 1) << 3) + (lane & 7)) * ROWB
                                + ((lane >> 4) << 4));

    for (int i = 0; i < niter; i++) {
        int s = i & 1;
        if (i + 1 < niter) {
            load_kv(sb, s ^ 1, b, (i + 1) * 64, t);
            CPA_COMMIT();
            CPA_WAIT1();
        } else {
            CPA_WAIT0();
        }
        __syncthreads();
        uint32_t sK = sb + STAGE0 + s * (2 * KT_B);
        uint32_t sV = sK + KT_B;

        // diagonal block-skip: warp needs only nbmax of the 4 column blocks
        int j0 = i * 64;
        bool need_mask = (j0 >= q0);
        int nbmax = 4;
        if (need_mask) {
            int d = q0 + 16 * wq + 15 - j0;
            nbmax = (d < 0) ? 0 : min(4, (d >> 4) + 1);
        }

        if (nbmax > 0) {
            // ---- S = Q K^T (only live column blocks) ----
            float sacc[8][4];
#pragma unroll
            for (int f = 0; f < 8; f++)
#pragma unroll
                for (int q = 0; q < 4; q++) sacc[f][q] = 0.f;
#pragma unroll
            for (int ks = 0; ks < 8; ks++) {
                uint32_t qh[4];
                ldm_x4(qh, sb + aoff + ks * 32);
#pragma unroll
                for (int nblk = 0; nblk < 4; nblk++) {
                    if (nblk >= nbmax) break;
                    uint32_t kh[4];
                    ldm_x4(kh, sK + nblk * (16 * ROWB) + boffK + ks * 32);
                    mma_f16(sacc[2 * nblk],     qh, kh);
                    mma_f16(sacc[2 * nblk + 1], qh, kh + 2);
                }
            }

            // ---- online softmax (base-2 domain) ----
            int fmax = 2 * nbmax;
            float rm1 = -INFINITY, rm2 = -INFINITY;
#pragma unroll
            for (int f = 0; f < 8; f++) {
                if (f >= fmax) break;
                int c0 = j0 + 8 * f + ((lane & 3) << 1);
                float s0 = sacc[f][0] * scale, s1 = sacc[f][1] * scale;
                float s2 = sacc[f][2] * scale, s3 = sacc[f][3] * scale;
                if (need_mask) {
                    if (c0     > grow1) s0 = -INFINITY;
                    if (c0 + 1 > grow1) s1 = -INFINITY;
                    if (c0     > grow2) s2 = -INFINITY;
                    if (c0 + 1 > grow2) s3 = -INFINITY;
                }
                sacc[f][0] = s0; sacc[f][1] = s1; sacc[f][2] = s2; sacc[f][3] = s3;
                rm1 = fmaxf(rm1, fmaxf(s0, s1));
                rm2 = fmaxf(rm2, fmaxf(s2, s3));
            }
            rm1 = fmaxf(rm1, __shfl_xor_sync(0xffffffffu, rm1, 1));
            rm1 = fmaxf(rm1, __shfl_xor_sync(0xffffffffu, rm1, 2));
            rm2 = fmaxf(rm2, __shfl_xor_sync(0xffffffffu, rm2, 1));
            rm2 = fmaxf(rm2, __shfl_xor_sync(0xffffffffu, rm2, 2));
            float mn1 = fmaxf(m1, rm1), mn2 = fmaxf(m2, rm2);
            float cor1 = ex2(m1 - mn1), cor2 = ex2(m2 - mn2);
            m1 = mn1; m2 = mn2;

            float rs1 = 0.f, rs2 = 0.f;
            uint32_t ph[8], ph2[8];
#pragma unroll
            for (int f = 0; f < 8; f++) {
                if (f >= fmax) break;
                float p0 = ex2(sacc[f][0] - m1);
                float p1 = ex2(sacc[f][1] - m1);
                float p2 = ex2(sacc[f][2] - m2);
                float p3 = ex2(sacc[f][3] - m2);
                rs1 += p0 + p1; rs2 += p2 + p3;
                ph[f]  = packh2(p0, p1);
                ph2[f] = packh2(p2, p3);
            }
            rs1 += __shfl_xor_sync(0xffffffffu, rs1, 1);
            rs1 += __shfl_xor_sync(0xffffffffu, rs1, 2);
            rs2 += __shfl_xor_sync(0xffffffffu, rs2, 1);
            rs2 += __shfl_xor_sync(0xffffffffu, rs2, 2);
            l1 = l1 * cor1 + rs1;
            l2 = l2 * cor2 + rs2;
#pragma unroll
            for (int f = 0; f < 16; f++) {
                o[f][0] *= cor1; o[f][1] *= cor1;
                o[f][2] *= cor2; o[f][3] *= cor2;
            }

            // ---- O += P V (only live kk blocks) ----
#pragma unroll
            for (int kk = 0; kk < 4; kk++) {
                if (kk >= nbmax) break;
                uint32_t a[4] = {ph[2 * kk], ph2[2 * kk],
                                 ph[2 * kk + 1], ph2[2 * kk + 1]};
#pragma unroll
                for (int dg = 0; dg < 8; dg++) {
                    uint32_t vh[4];
                    ldm_x4_t(vh, sV + kk * (16 * ROWB) + voff + dg * 32);
                    mma_f16(o[2 * dg],     a, vh);
                    mma_f16(o[2 * dg + 1], a, vh + 2);
                }
            }
        }
        __syncthreads();
    }

    // epilogue
    float inv1 = 1.f / l1, inv2 = 1.f / l2;
    float* o1 = out + ((size_t)(b * L + grow1)) * (NH * HD) + h * HD;
    float* o2 = out + ((size_t)(b * L + grow2)) * (NH * HD) + h * HD;
#pragma unroll
    for (int f = 0; f < 16; f++) {
        int d = 8 * f + ((lane & 3) << 1);
        *(float2*)(o1 + d) = make_float2(o[f][0] * inv1, o[f][1] * inv1);
        *(float2*)(o2 + d) = make_float2(o[f][2] * inv2, o[f][3] * inv2);
    }
}

// ---------------- launch --------------------------------------------------------
extern "C" void kernel_launch(void* const* d_in, const int* in_sizes, int n_in,
                              void* d_out, int out_size) {
    const float* x  = (const float*)d_in[0];
    const float* Wq = (const float*)d_in[1];
    const float* Wk = (const float*)d_in[2];
    const float* Wv = (const float*)d_in[3];
    float* out = (float*)d_out;

    (void)cudaFuncSetAttribute(qkv_gemm_kernel,
                               cudaFuncAttributeMaxDynamicSharedMemorySize, 110592);
    (void)cudaFuncSetAttribute(attn_kernel,
                               cudaFuncAttributeMaxDynamicSharedMemorySize, 139264);

    prep_kernel<<<13312, 256>>>(x, Wq, Wk, Wv);
    qkv_gemm_kernel<<<dim3(18, 32), 256, 110592>>>();
    attn_kernel<<<dim3(8, NH, B), 512, 139264>>>(out);
}

// round 13
// speedup vs baseline: 1.2378x; 1.2378x over previous
#include <cuda_runtime.h>
#include <cuda_fp16.h>
#include <math.h>
#include <stdint.h>

#define B   2
#define L   2048
#define EMB 2048
#define NH  16
#define HD  128
#define NTOT 2304          // 2048 Q cols + 128 K + 128 V

// ---------------- scratch (device globals: no allocation allowed) -------------
__device__ __half g_Qh[2 * 16 * 2048 * 128];  // [B][NH][L][HD] RoPE'd fp16
__device__ __half g_Kh[2 * 2048 * 128];       // [B][L][HD] RoPE'd
__device__ __half g_Vh[2 * 2048 * 128];
__device__ float  g_Rc[2048 * 64];
__device__ float  g_Rs[2048 * 64];
__device__ __half g_Xh[4096 * 2048];          // X fp16
__device__ __half g_Wth[NTOT * 2048];         // W^T fp16 [n][k]

// ---------------- PTX helpers ---------------------------------------------------
__device__ __forceinline__ uint32_t smem_u32(const void* p) {
    uint32_t a;
    asm("{ .reg .u64 t; cvta.to.shared.u64 t, %1; cvt.u32.u64 %0, t; }" : "=r"(a) : "l"(p));
    return a;
}
__device__ __forceinline__ void cpa16(uint32_t dst, const void* src) {
    asm volatile("cp.async.cg.shared.global [%0], [%1], 16;" :: "r"(dst), "l"(src));
}
#define CPA_COMMIT() asm volatile("cp.async.commit_group;" ::: "memory")
#define CPA_WAIT0()  asm volatile("cp.async.wait_group 0;" ::: "memory")
#define CPA_WAIT1()  asm volatile("cp.async.wait_group 1;" ::: "memory")

__device__ __forceinline__ void ldm_x4(uint32_t* r, uint32_t addr) {
    asm volatile("ldmatrix.sync.aligned.m8n8.x4.shared.b16 {%0,%1,%2,%3}, [%4];"
        : "=r"(r[0]), "=r"(r[1]), "=r"(r[2]), "=r"(r[3]) : "r"(addr));
}
__device__ __forceinline__ void ldm_x4_t(uint32_t* r, uint32_t addr) {
    asm volatile("ldmatrix.sync.aligned.m8n8.x4.trans.shared.b16 {%0,%1,%2,%3}, [%4];"
        : "=r"(r[0]), "=r"(r[1]), "=r"(r[2]), "=r"(r[3]) : "r"(addr));
}
__device__ __forceinline__ void mma_f16(float* c, const uint32_t* a, const uint32_t* b) {
    asm volatile("mma.sync.aligned.m16n8k16.row.col.f32.f16.f16.f32 "
        "{%0,%1,%2,%3}, {%4,%5,%6,%7}, {%8,%9}, {%0,%1,%2,%3};"
        : "+f"(c[0]), "+f"(c[1]), "+f"(c[2]), "+f"(c[3])
        : "r"(a[0]), "r"(a[1]), "r"(a[2]), "r"(a[3]), "r"(b[0]), "r"(b[1]));
}
__device__ __forceinline__ uint32_t packh2(float a, float b) {
    __half2 h = __floats2half2_rn(a, b);
    return *(uint32_t*)&h;
}
__device__ __forceinline__ float ex2(float x) {
    float y;
    asm("ex2.approx.f32 %0, %1;" : "=f"(y) : "f"(x));
    return y;
}

// ---------------- fused prepass: rope table | X fp16 | W^T fp16 -----------------
__global__ void prep_kernel(const float* __restrict__ X,
                            const float* __restrict__ Wq,
                            const float* __restrict__ Wk,
                            const float* __restrict__ Wv) {
    __shared__ float tile[32][33];
    int bid = blockIdx.x;
    if (bid < 512) {
        int idx = bid * 256 + threadIdx.x;        // 2048*64
        int l = idx >> 6;
        int i = idx & 63;
        double invf = pow(10000.0, -(double)(2 * i) / (double)HD);
        double a = (double)l * invf;
        g_Rc[idx] = (float)cos(a);
        g_Rs[idx] = (float)sin(a);
    } else if (bid < 512 + 8192) {
        int i = ((bid - 512) * 256 + threadIdx.x) * 4;
        float4 v = *(const float4*)(X + i);
        float vv[4] = {v.x, v.y, v.z, v.w};
        __half h[4];
#pragma unroll
        for (int j = 0; j < 4; j++) h[j] = __float2half_rn(vv[j]);
        *(uint2*)(g_Xh + i) = *(uint2*)h;
    } else {
        int r = bid - 8704;
        int kb = (r & 63) * 32;
        int nb = (r >> 6) * 32;
        const float* W; int ldw, n0;
        if (nb < 2048)      { W = Wq; ldw = 2048; n0 = nb; }
        else if (nb < 2176) { W = Wk; ldw = 128;  n0 = nb - 2048; }
        else                { W = Wv; ldw = 128;  n0 = nb - 2176; }
        int tx = threadIdx.x & 31, ty = threadIdx.x >> 5;
#pragma unroll
        for (int rr = 0; rr < 32; rr += 8)
            tile[ty + rr][tx] = W[(size_t)(kb + ty + rr) * ldw + n0 + tx];
        __syncthreads();
#pragma unroll
        for (int rr = 0; rr < 32; rr += 8)
            g_Wth[(size_t)(nb + ty + rr) * 2048 + kb + tx] =
                __float2half_rn(tile[tx][ty + rr]);
    }
}

// ---------------- QKV GEMM: fp16 mma.sync, BK=64, 3-stage pipeline --------------
// Grid (18, 32), 256 thr = 8 warps (4m x 2n). Tile 128x128, BK=64.
// smem/stage: Xh | Wh tiles, 128 rows x 144B each; 3 stages = 110592B.
#define TS      144
#define TILE_B  (128 * TS)          // 18432
#define STG_B   (2 * TILE_B)        // 36864
#define NCHUNK  32

__device__ __forceinline__ void load_chunk(uint32_t sbase, int stage,
                                           int m0, int n0, int kc, int t) {
    uint32_t sb = sbase + stage * STG_B;
#pragma unroll
    for (int it = 0; it < 8; it++) {
        int g = t + 256 * it;               // 0..2047
        int tile = g >> 10;
        int r = (g >> 3) & 127;
        int c = g & 7;
        uint32_t dst = sb + tile * TILE_B + r * TS + c * 16;
        const __half* src;
        if (tile == 0) src = g_Xh  + (size_t)(m0 + r) * EMB + kc + c * 8;
        else           src = g_Wth + (size_t)(n0 + r) * EMB + kc + c * 8;
        cpa16(dst, src);
    }
}

__global__ __launch_bounds__(256, 2) void qkv_gemm_kernel() {
    extern __shared__ char smem[];
    uint32_t sbase = smem_u32(smem);
    int t = threadIdx.x;
    int lane = t & 31, w = t >> 5;
    int wm = w & 3, wn = w >> 2;
    int nb = blockIdx.x;
    int m0 = blockIdx.y * 128;
    int n0 = nb * 128;

    float acc[2][8][4];
#pragma unroll
    for (int i = 0; i < 2; i++)
#pragma unroll
        for (int j = 0; j < 8; j++)
#pragma unroll
            for (int q = 0; q < 4; q++) acc[i][j][q] = 0.f;

    int aRow = wm * 32 + (lane & 15);
    uint32_t aOff = (uint32_t)(aRow * TS + ((lane >> 4) << 4));
    int bRow = wn * 64 + ((lane >> 4) << 3) + (lane & 7);
    uint32_t bOff = (uint32_t)(bRow * TS + (((lane >> 3) & 1) << 4));

    load_chunk(sbase, 0, m0, n0, 0, t);
    CPA_COMMIT();
    load_chunk(sbase, 1, m0, n0, 64, t);
    CPA_COMMIT();

    for (int i = 0; i < NCHUNK; i++) {
        if (i < NCHUNK - 1) CPA_WAIT1(); else CPA_WAIT0();
        __syncthreads();
        if (i + 2 < NCHUNK) {
            load_chunk(sbase, (i + 2) % 3, m0, n0, (i + 2) * 64, t);
            CPA_COMMIT();
        }

        uint32_t sb = sbase + (i % 3) * STG_B;
#pragma unroll
        for (int ks = 0; ks < 4; ks++) {
            uint32_t kb = ks * 32;
            uint32_t ah[2][4];
#pragma unroll
            for (int mf = 0; mf < 2; mf++)
                ldm_x4(ah[mf], sb + aOff + (uint32_t)(mf * 16 * TS) + kb);
#pragma unroll
            for (int ng = 0; ng < 4; ng++) {
                uint32_t bh[4];
                ldm_x4(bh, sb + TILE_B + bOff + (uint32_t)(ng * 16 * TS) + kb);
#pragma unroll
                for (int sub = 0; sub < 2; sub++) {
                    int nf = ng * 2 + sub;
                    mma_f16(acc[0][nf], ah[0], bh + 2 * sub);
                    mma_f16(acc[1][nf], ah[1], bh + 2 * sub);
                }
            }
        }
    }

    // epilogue: RoPE (Q,K) + fp16 scatter
#pragma unroll
    for (int mf = 0; mf < 2; mf++) {
#pragma unroll
        for (int half = 0; half < 2; half++) {
            int row = m0 + wm * 32 + mf * 16 + (lane >> 2) + half * 8;
            int bb = row >> 11;
            int l  = row & 2047;
#pragma unroll
            for (int nf = 0; nf < 8; nf++) {
                int dcol = wn * 64 + nf * 8 + ((lane & 3) << 1);
                float e = acc[mf][nf][half * 2 + 0];
                float o = acc[mf][nf][half * 2 + 1];
                float2 v;
                if (nb != 17) {
                    float c  = g_Rc[l * 64 + (dcol >> 1)];
                    float sn = g_Rs[l * 64 + (dcol >> 1)];
                    v.x = e * c - o * sn;
                    v.y = o * c + e * sn;
                } else {
                    v.x = e; v.y = o;
                }
                __half2 hp = __floats2half2_rn(v.x, v.y);
                if (nb < 16)
                    *(__half2*)(g_Qh + ((size_t)(bb * NH + nb) * L + l) * HD + dcol) = hp;
                else if (nb == 16)
                    *(__half2*)(g_Kh + (size_t)row * HD + dcol) = hp;
                else
                    *(__half2*)(g_Vh + (size_t)row * HD + dcol) = hp;
            }
        }
    }
}

// ---------------- causal flash attention: fp16 mma.sync, 2 CTA/SM ---------------
// qt-PAIRED: each CTA runs qt_a = 8+bx (heavy) then qt_b = 7-bx (light);
// every pair = exactly 34 iterations -> 256 equal CTAs, single wave.
#define ROWB 272
#define QT_B 34816
#define KT_B 17408
#define STAGE0 34816

__device__ __forceinline__ void load_kv(uint32_t sb, int stage, int b, int j0, int t) {
    uint32_t base = sb + STAGE0 + stage * (2 * KT_B);
#pragma unroll
    for (int it = 0; it < 8; it++) {
        int g = t + 256 * it;             // 0..2047
        int tile = g >> 10;               // K, V
        int r = (g >> 4) & 63;
        int c = g & 15;
        size_t off = (size_t)(b * L + j0 + r) * HD + c * 8;
        const __half* src = (tile ? g_Vh : g_Kh) + off;
        cpa16(base + tile * KT_B + r * ROWB + c * 16, src);
    }
}

__global__ __launch_bounds__(256, 2) void attn_kernel(float* __restrict__ out) {
    extern __shared__ char sm[];
    uint32_t sb = smem_u32(sm);
    int t = threadIdx.x;
    int lane = t & 31, wq = t >> 5;
    int h = blockIdx.y, b = blockIdx.z;

    const float scale = 0.08838834764831845f * 1.44269504088896f;  // /sqrt(HD)*log2e
    uint32_t aoff  = (uint32_t)((wq * 16 + (lane & 15)) * ROWB + ((lane >> 4) << 4));
    uint32_t boffK = (uint32_t)((((lane >> 4) << 3) + (lane & 7)) * ROWB
                                + (((lane >> 3) & 1) << 4));
    uint32_t voff  = (uint32_t)(((((lane >> 3) & 1) << 3) + (lane & 7)) * ROWB
                                + ((lane >> 4) << 4));

#pragma unroll 1
    for (int tile2 = 0; tile2 < 2; tile2++) {
        int qt = tile2 == 0 ? 8 + blockIdx.x : 7 - blockIdx.x;
        int q0 = qt * 128;

        // load Q tile + first KV stage (one cp.async group)
        {
            const __half* Qp = g_Qh + ((size_t)(b * NH + h) * L + q0) * HD;
#pragma unroll
            for (int it = 0; it < 8; it++) {
                int g = t + 256 * it;
                int r = g >> 4;
                int c = g & 15;
                cpa16(sb + r * ROWB + c * 16, Qp + (size_t)r * HD + c * 8);
            }
        }
        load_kv(sb, 0, b, 0, t);
        CPA_COMMIT();

        float o[16][4];
#pragma unroll
        for (int i = 0; i < 16; i++)
#pragma unroll
            for (int j = 0; j < 4; j++) o[i][j] = 0.f;
        float m1 = -INFINITY, m2 = -INFINITY, l1 = 0.f, l2 = 0.f;

        int niter = 2 * qt + 2;
        int grow1 = q0 + wq * 16 + (lane >> 2);
        int grow2 = grow1 + 8;

        for (int i = 0; i < niter; i++) {
            int s = i & 1;
            if (i + 1 < niter) {
                load_kv(sb, s ^ 1, b, (i + 1) * 64, t);
                CPA_COMMIT();
                CPA_WAIT1();
            } else {
                CPA_WAIT0();
            }
            __syncthreads();
            uint32_t sK = sb + STAGE0 + s * (2 * KT_B);
            uint32_t sV = sK + KT_B;

            // diagonal block-skip: warp needs only nbmax of the 4 column blocks
            int j0 = i * 64;
            bool need_mask = (j0 >= q0);
            int nbmax = 4;
            if (need_mask) {
                int d = q0 + 16 * wq + 15 - j0;
                nbmax = (d < 0) ? 0 : min(4, (d >> 4) + 1);
            }

            if (nbmax > 0) {
                // ---- S = Q K^T (only live column blocks) ----
                float sacc[8][4];
#pragma unroll
                for (int f = 0; f < 8; f++)
#pragma unroll
                    for (int q = 0; q < 4; q++) sacc[f][q] = 0.f;
#pragma unroll
                for (int ks = 0; ks < 8; ks++) {
                    uint32_t qh[4];
                    ldm_x4(qh, sb + aoff + ks * 32);
#pragma unroll
                    for (int nblk = 0; nblk < 4; nblk++) {
                        if (nblk >= nbmax) break;
                        uint32_t kh[4];
                        ldm_x4(kh, sK + nblk * (16 * ROWB) + boffK + ks * 32);
                        mma_f16(sacc[2 * nblk],     qh, kh);
                        mma_f16(sacc[2 * nblk + 1], qh, kh + 2);
                    }
                }

                // ---- online softmax (base-2 domain) ----
                int fmax = 2 * nbmax;
                float rm1 = -INFINITY, rm2 = -INFINITY;
#pragma unroll
                for (int f = 0; f < 8; f++) {
                    if (f >= fmax) break;
                    int c0 = j0 + 8 * f + ((lane & 3) << 1);
                    float s0 = sacc[f][0] * scale, s1 = sacc[f][1] * scale;
                    float s2 = sacc[f][2] * scale, s3 = sacc[f][3] * scale;
                    if (need_mask) {
                        if (c0     > grow1) s0 = -INFINITY;
                        if (c0 + 1 > grow1) s1 = -INFINITY;
                        if (c0     > grow2) s2 = -INFINITY;
                        if (c0 + 1 > grow2) s3 = -INFINITY;
                    }
                    sacc[f][0] = s0; sacc[f][1] = s1; sacc[f][2] = s2; sacc[f][3] = s3;
                    rm1 = fmaxf(rm1, fmaxf(s0, s1));
                    rm2 = fmaxf(rm2, fmaxf(s2, s3));
                }
                rm1 = fmaxf(rm1, __shfl_xor_sync(0xffffffffu, rm1, 1));
                rm1 = fmaxf(rm1, __shfl_xor_sync(0xffffffffu, rm1, 2));
                rm2 = fmaxf(rm2, __shfl_xor_sync(0xffffffffu, rm2, 1));
                rm2 = fmaxf(rm2, __shfl_xor_sync(0xffffffffu, rm2, 2));
                float mn1 = fmaxf(m1, rm1), mn2 = fmaxf(m2, rm2);
                float cor1 = ex2(m1 - mn1), cor2 = ex2(m2 - mn2);
                m1 = mn1; m2 = mn2;

                float rs1 = 0.f, rs2 = 0.f;
                uint32_t ph[8], ph2[8];
#pragma unroll
                for (int f = 0; f < 8; f++) {
                    if (f >= fmax) break;
                    float p0 = ex2(sacc[f][0] - m1);
                    float p1 = ex2(sacc[f][1] - m1);
                    float p2 = ex2(sacc[f][2] - m2);
                    float p3 = ex2(sacc[f][3] - m2);
                    rs1 += p0 + p1; rs2 += p2 + p3;
                    ph[f]  = packh2(p0, p1);
                    ph2[f] = packh2(p2, p3);
                }
                rs1 += __shfl_xor_sync(0xffffffffu, rs1, 1);
                rs1 += __shfl_xor_sync(0xffffffffu, rs1, 2);
                rs2 += __shfl_xor_sync(0xffffffffu, rs2, 1);
                rs2 += __shfl_xor_sync(0xffffffffu, rs2, 2);
                l1 = l1 * cor1 + rs1;
                l2 = l2 * cor2 + rs2;
#pragma unroll
                for (int f = 0; f < 16; f++) {
                    o[f][0] *= cor1; o[f][1] *= cor1;
                    o[f][2] *= cor2; o[f][3] *= cor2;
                }

                // ---- O += P V (only live kk blocks) ----
#pragma unroll
                for (int kk = 0; kk < 4; kk++) {
                    if (kk >= nbmax) break;
                    uint32_t a[4] = {ph[2 * kk], ph2[2 * kk],
                                     ph[2 * kk + 1], ph2[2 * kk + 1]};
#pragma unroll
                    for (int dg = 0; dg < 8; dg++) {
                        uint32_t vh[4];
                        ldm_x4_t(vh, sV + kk * (16 * ROWB) + voff + dg * 32);
                        mma_f16(o[2 * dg],     a, vh);
                        mma_f16(o[2 * dg + 1], a, vh + 2);
                    }
                }
            }
            __syncthreads();
        }

        // epilogue for this q-tile
        float inv1 = 1.f / l1, inv2 = 1.f / l2;
        float* o1 = out + ((size_t)(b * L + grow1)) * (NH * HD) + h * HD;
        float* o2 = out + ((size_t)(b * L + grow2)) * (NH * HD) + h * HD;
#pragma unroll
        for (int f = 0; f < 16; f++) {
            int d = 8 * f + ((lane & 3) << 1);
            *(float2*)(o1 + d) = make_float2(o[f][0] * inv1, o[f][1] * inv1);
            *(float2*)(o2 + d) = make_float2(o[f][2] * inv2, o[f][3] * inv2);
        }
    }
}

// ---------------- launch --------------------------------------------------------
extern "C" void kernel_launch(void* const* d_in, const int* in_sizes, int n_in,
                              void* d_out, int out_size) {
    const float* x  = (const float*)d_in[0];
    const float* Wq = (const float*)d_in[1];
    const float* Wk = (const float*)d_in[2];
    const float* Wv = (const float*)d_in[3];
    float* out = (float*)d_out;

    (void)cudaFuncSetAttribute(qkv_gemm_kernel,
                               cudaFuncAttributeMaxDynamicSharedMemorySize, 110592);
    (void)cudaFuncSetAttribute(attn_kernel,
                               cudaFuncAttributeMaxDynamicSharedMemorySize, 104448);

    prep_kernel<<<13312, 256>>>(x, Wq, Wk, Wv);
    qkv_gemm_kernel<<<dim3(18, 32), 256, 110592>>>();
    attn_kernel<<<dim3(8, NH, B), 256, 104448>>>(out);
}